// round 15
// baseline (speedup 1.0000x reference)
#include <cuda_runtime.h>
#include <cuda_bf16.h>
#include <cstdint>

#define MAX_N 100000
#define MAX_E 2000000
#define F 128

// ---------------- device scratch (no allocations allowed) ----------------
__device__ int   g_cnt[MAX_N];             // in-degree (int)
__device__ int   g_off[MAX_N];             // CSR offsets
__device__ int   g_cur[MAX_N];             // fill cursors
__device__ int   g_bsum[1024];             // block sums for scan
__device__ float g_dis[MAX_N];             // deg_inv_sqrt
__device__ int2  g_epack[MAX_E];           // (src, norm bits) grouped by dst
__device__ float g_h  [(size_t)MAX_N * F]; // GEMM output (per layer)
__device__ float g_x2 [(size_t)MAX_N * F]; // layer-1 activation
__device__ int   g_is64;                   // 1 if edge_index is int64

// ---------------- helpers ----------------
__device__ __forceinline__ int load_idx(const void* ei, long long pos) {
    if (g_is64) return (int)((const long long*)ei)[pos];
    return ((const int*)ei)[pos];
}

// ---------------- fused zero + dtype sniff ----------------
__global__ void zero_detect_kernel(const void* ei, int n) {
    int i = blockIdx.x * blockDim.x + threadIdx.x;
    if (i < n) g_cnt[i] = 0;
    if (i == 0) {
        const int* w = (const int*)ei;
        int all_zero = 1;
        // values in [0, 100000): int64 hi-words are 0; false-positive ~0.
        for (int j = 1; j < 64; j += 2) all_zero &= (w[j] == 0);
        g_is64 = all_zero;
    }
}

// ---------------- degree accumulation (dst side, int) ----------------
__global__ void deg_kernel(const void* __restrict__ ei, int E) {
    int i = blockIdx.x * blockDim.x + threadIdx.x;
    if (i >= E) return;
    atomicAdd(&g_cnt[load_idx(ei, (long long)E + i)], 1);
}

// ---------------- scan1 fused with deg_inv_sqrt ----------------
__global__ void scan1_dis_kernel(int n) {
    __shared__ int sm[256];
    int t = threadIdx.x;
    int i = blockIdx.x * 256 + t;
    int v = (i < n) ? g_cnt[i] : 0;
    if (i < n) g_dis[i] = rsqrtf((float)v + 1.0f);
    sm[t] = v;
    __syncthreads();
    for (int off = 128; off > 0; off >>= 1) {
        if (t < off) sm[t] += sm[t + off];
        __syncthreads();
    }
    if (t == 0) g_bsum[blockIdx.x] = sm[0];
}

__global__ void scan2_kernel(int nb) {
    __shared__ int sm[1024];
    int t = threadIdx.x;
    int v = (t < nb) ? g_bsum[t] : 0;
    sm[t] = v;
    __syncthreads();
    for (int off = 1; off < 1024; off <<= 1) {
        int add = (t >= off) ? sm[t - off] : 0;
        __syncthreads();
        sm[t] += add;
        __syncthreads();
    }
    if (t < nb) g_bsum[t] = sm[t] - v;   // exclusive
}

__global__ void scan3_kernel(int n) {
    __shared__ int sm[256];
    int t = threadIdx.x;
    int i = blockIdx.x * 256 + t;
    int v = (i < n) ? g_cnt[i] : 0;
    sm[t] = v;
    __syncthreads();
    for (int off = 1; off < 256; off <<= 1) {
        int add = (t >= off) ? sm[t - off] : 0;
        __syncthreads();
        sm[t] += add;
        __syncthreads();
    }
    if (i < n) {
        int o = g_bsum[blockIdx.x] + sm[t] - v;   // exclusive
        g_off[i] = o;
        g_cur[i] = o;
    }
}

__global__ void fill_kernel(const void* __restrict__ ei, int E) {
    int i = blockIdx.x * blockDim.x + threadIdx.x;
    if (i >= E) return;
    int s = load_idx(ei, i);
    int d = load_idx(ei, (long long)E + i);
    float norm = g_dis[s] * g_dis[d];
    int pos = atomicAdd(&g_cur[d], 1);
    g_epack[pos] = make_int2(s, __float_as_int(norm));
}

// ---------------- HMMA GEMM: O[M,128] = X[M,128] @ W[128,128]^T -----------
// R14 redesign of the R7 mma.sync kernel (which was CORRECT, rel_err 4.3e-6,
// but 1 CTA/SM at 139 KB smem). 64x64 output tile per CTA:
//   smem = 4 x [64][TP] bf16 = 69.6 KB -> 3 CTAs/SM (24 warps).
// 3-term bf16 split (Ahi*Whi + Ahi*Wlo + Alo*Whi) in fp32 accumulators.
// Fragment offsets identical to R7 (proven); TP=136 => conflict-free frag LDS.
#define TP 136
static constexpr int GEMM_SMEM = 4 * 64 * TP * 2;   // 69632 B

__device__ __forceinline__ void mma16816(float* d, const uint32_t* a,
                                         const uint32_t* b) {
    asm volatile(
        "mma.sync.aligned.m16n8k16.row.col.f32.bf16.bf16.f32 "
        "{%0,%1,%2,%3}, {%4,%5,%6,%7}, {%8,%9}, {%0,%1,%2,%3};"
        : "+f"(d[0]), "+f"(d[1]), "+f"(d[2]), "+f"(d[3])
        : "r"(a[0]), "r"(a[1]), "r"(a[2]), "r"(a[3]), "r"(b[0]), "r"(b[1]));
}

__device__ __forceinline__ uint32_t pack_hi(float a, float b) {
    __nv_bfloat16 ha = __float2bfloat16(a);
    __nv_bfloat16 hb = __float2bfloat16(b);
    return (uint32_t)__bfloat16_as_ushort(ha) |
           ((uint32_t)__bfloat16_as_ushort(hb) << 16);
}
__device__ __forceinline__ uint32_t pack_lo(float a, float b) {
    __nv_bfloat16 ha = __float2bfloat16(a);
    __nv_bfloat16 hb = __float2bfloat16(b);
    __nv_bfloat16 la = __float2bfloat16(a - __bfloat162float(ha));
    __nv_bfloat16 lb = __float2bfloat16(b - __bfloat162float(hb));
    return (uint32_t)__bfloat16_as_ushort(la) |
           ((uint32_t)__bfloat16_as_ushort(lb) << 16);
}

__global__ __launch_bounds__(256, 3)
void gemm_mma_kernel(const float* __restrict__ X, const float* __restrict__ W,
                     float* __restrict__ O, int M) {
    extern __shared__ __nv_bfloat16 smb[];
    __nv_bfloat16* sAh = smb;                  // [64][TP]
    __nv_bfloat16* sAl = sAh + 64 * TP;
    __nv_bfloat16* sWh = sAl + 64 * TP;        // [64][TP] (64 output cols)
    __nv_bfloat16* sWl = sWh + 64 * TP;

    int t = threadIdx.x;
    int row0 = blockIdx.x * 64;
    int col0 = blockIdx.y * 64;

    const float4* X4 = (const float4*)X;
    const float4* W4 = (const float4*)W;

    // ---- stage + hi/lo split-convert A tile (64 rows of X) ----
    for (int idx = t; idx < 64 * 32; idx += 256) {
        int r = idx >> 5, c4 = idx & 31;
        int gr = row0 + r;
        float4 av = (gr < M) ? X4[(size_t)gr * 32 + c4]
                             : make_float4(0.f, 0.f, 0.f, 0.f);
        int base = r * TP + c4 * 4;
        *(uint32_t*)&sAh[base]     = pack_hi(av.x, av.y);
        *(uint32_t*)&sAh[base + 2] = pack_hi(av.z, av.w);
        *(uint32_t*)&sAl[base]     = pack_lo(av.x, av.y);
        *(uint32_t*)&sAl[base + 2] = pack_lo(av.z, av.w);
    }
    // ---- stage + split-convert W half-tile (64 output cols) ----
    for (int idx = t; idx < 64 * 32; idx += 256) {
        int j = idx >> 5, c4 = idx & 31;
        float4 wv = W4[(size_t)(col0 + j) * 32 + c4];
        int base = j * TP + c4 * 4;
        *(uint32_t*)&sWh[base]     = pack_hi(wv.x, wv.y);
        *(uint32_t*)&sWh[base + 2] = pack_hi(wv.z, wv.w);
        *(uint32_t*)&sWl[base]     = pack_lo(wv.x, wv.y);
        *(uint32_t*)&sWl[base + 2] = pack_lo(wv.z, wv.w);
    }
    __syncthreads();

    // ---- warp tiling: 8 warps = 4 (M, 16 rows each) x 2 (N, 32 cols each) --
    int wid = t >> 5, lane = t & 31;
    int wm = wid & 3;
    int wn = wid >> 2;
    int lrow = lane >> 2;       // 0..7
    int lkc  = (lane & 3) * 2;  // 0,2,4,6

    float acc[4][4];
    #pragma unroll
    for (int nt = 0; nt < 4; nt++)
        #pragma unroll
        for (int q = 0; q < 4; q++) acc[nt][q] = 0.f;

    #pragma unroll
    for (int k = 0; k < 128; k += 16) {
        // A fragments (m16k16), hi+lo — R7-proven offsets
        int r = wm * 16 + lrow;
        int o0 = r * TP + k + lkc;
        uint32_t ah[4], al[4];
        ah[0] = *(const uint32_t*)&sAh[o0];
        ah[1] = *(const uint32_t*)&sAh[o0 + 8 * TP];
        ah[2] = *(const uint32_t*)&sAh[o0 + 8];
        ah[3] = *(const uint32_t*)&sAh[o0 + 8 * TP + 8];
        al[0] = *(const uint32_t*)&sAl[o0];
        al[1] = *(const uint32_t*)&sAl[o0 + 8 * TP];
        al[2] = *(const uint32_t*)&sAl[o0 + 8];
        al[3] = *(const uint32_t*)&sAl[o0 + 8 * TP + 8];
        #pragma unroll
        for (int nt = 0; nt < 4; nt++) {
            int j = wn * 32 + nt * 8 + lrow;
            int ob = j * TP + k + lkc;
            uint32_t bh[2], bl[2];
            bh[0] = *(const uint32_t*)&sWh[ob];
            bh[1] = *(const uint32_t*)&sWh[ob + 8];
            bl[0] = *(const uint32_t*)&sWl[ob];
            bl[1] = *(const uint32_t*)&sWl[ob + 8];
            mma16816(acc[nt], ah, bh);
            mma16816(acc[nt], ah, bl);
            mma16816(acc[nt], al, bh);
        }
    }

    // ---- epilogue: direct fp32 stores ----
    {
        int r = row0 + wm * 16 + lrow;
        #pragma unroll
        for (int nt = 0; nt < 4; nt++) {
            int c = col0 + wn * 32 + nt * 8 + lkc;
            if (r < M)
                *(float2*)&O[(size_t)r * 128 + c] =
                    make_float2(acc[nt][0], acc[nt][1]);
            if (r + 8 < M)
                *(float2*)&O[(size_t)(r + 8) * 128 + c] =
                    make_float2(acc[nt][2], acc[nt][3]);
        }
    }
}

// ---------------- fused gather-aggregate + self-loop + bias + leaky ------
// One warp per dst node (proven R5 version: 2-edge unroll).
__global__ __launch_bounds__(256)
void agg_kernel(const float* __restrict__ h, const float* __restrict__ b,
                float* __restrict__ out, int n) {
    int w    = (blockIdx.x * blockDim.x + threadIdx.x) >> 5;
    int lane = threadIdx.x & 31;
    if (w >= n) return;

    int beg = g_off[w];
    int cnt = g_cnt[w];
    const float4* h4 = (const float4*)h;

    float4 acc = make_float4(0.f, 0.f, 0.f, 0.f);

    int e = 0;
    for (; e + 2 <= cnt; e += 2) {
        int2 p0 = g_epack[beg + e];
        int2 p1 = g_epack[beg + e + 1];
        float n0 = __int_as_float(p0.y);
        float n1 = __int_as_float(p1.y);
        float4 v0 = h4[(size_t)p0.x * 32 + lane];
        float4 v1 = h4[(size_t)p1.x * 32 + lane];
        acc.x += v0.x * n0 + v1.x * n1;
        acc.y += v0.y * n0 + v1.y * n1;
        acc.z += v0.z * n0 + v1.z * n1;
        acc.w += v0.w * n0 + v1.w * n1;
    }
    if (e < cnt) {
        int2 p0 = g_epack[beg + e];
        float n0 = __int_as_float(p0.y);
        float4 v0 = h4[(size_t)p0.x * 32 + lane];
        acc.x += v0.x * n0;
        acc.y += v0.y * n0;
        acc.z += v0.z * n0;
        acc.w += v0.w * n0;
    }

    float dis = g_dis[w];
    float sw  = dis * dis;
    float4 hs = h4[(size_t)w * 32 + lane];
    float4 bb = ((const float4*)b)[lane];
    acc.x += hs.x * sw + bb.x;
    acc.y += hs.y * sw + bb.y;
    acc.z += hs.z * sw + bb.z;
    acc.w += hs.w * sw + bb.w;

    acc.x = (acc.x > 0.f) ? acc.x : 0.01f * acc.x;
    acc.y = (acc.y > 0.f) ? acc.y : 0.01f * acc.y;
    acc.z = (acc.z > 0.f) ? acc.z : 0.01f * acc.z;
    acc.w = (acc.w > 0.f) ? acc.w : 0.01f * acc.w;

    ((float4*)out)[(size_t)w * 32 + lane] = acc;
}

// ---------------- launch ----------------
extern "C" void kernel_launch(void* const* d_in, const int* in_sizes, int n_in,
                              void* d_out, int out_size) {
    const float* x  = (const float*)d_in[0];
    const void*  ei = d_in[1];
    const float* W1 = (const float*)d_in[2];
    const float* b1 = (const float*)d_in[3];
    const float* W2 = (const float*)d_in[4];
    const float* b2 = (const float*)d_in[5];
    float* out = (float*)d_out;

    int n = in_sizes[0] / F;
    int E = in_sizes[1] / 2;

    void *hp_v, *x2p_v;
    cudaGetSymbolAddress(&hp_v,  g_h);
    cudaGetSymbolAddress(&x2p_v, g_x2);
    float* hp  = (float*)hp_v;
    float* x2p = (float*)x2p_v;

    cudaFuncSetAttribute(gemm_mma_kernel,
                         cudaFuncAttributeMaxDynamicSharedMemorySize, GEMM_SMEM);

    int nb        = (n + 255) / 256;
    dim3 gemm_grid((n + 63) / 64, 2);
    int node_grid = (n + 255) / 256;
    int edge_grid = (E + 255) / 256;
    int agg_grid  = ((long long)n * 32 + 255) / 256;

    // gemm1 has no CSR dependency; kept as the 4th launch so ncu's window
    // profiles it next round (verify tensor-pipe activity + L1% drop).
    zero_detect_kernel<<<node_grid, 256>>>(ei, n);       // 1
    deg_kernel<<<edge_grid, 256>>>(ei, E);               // 2
    scan1_dis_kernel<<<nb, 256>>>(n);                    // 3
    gemm_mma_kernel<<<gemm_grid, 256, GEMM_SMEM>>>(x, W1, hp, n);  // 4 <- profiled
    scan2_kernel<<<1, 1024>>>(nb);                       // 5
    scan3_kernel<<<nb, 256>>>(n);                        // 6
    fill_kernel<<<edge_grid, 256>>>(ei, E);              // 7

    // layer 1 aggregation (needs gemm1 + CSR)
    agg_kernel<<<agg_grid, 256>>>(hp, b1, x2p, n);

    // layer 2
    gemm_mma_kernel<<<gemm_grid, 256, GEMM_SMEM>>>(x2p, W2, hp, n);
    agg_kernel<<<agg_grid, 256>>>(hp, b2, out, n);
}